// round 5
// baseline (speedup 1.0000x reference)
#include <cuda_runtime.h>
#include <cstdint>

#define B_N   65536
#define IN_N  512
#define H_N   1024
#define STEPS 10
#define BETA  0.9f
#define THR   1.0f

#define NSTRIPE 32                     // 1024 cols / 32
#define LISTW   1120                   // padded list length per (b,half)
#define NCHUNK  256                    // b-chunks of 256
#define NTASK   (NSTRIPE * NCHUNK)     // 8192
#define SWPITCH 36                     // floats per smem W2 row (32 + pad)
#define SMEMB   (1025 * SWPITCH * 4)   // 147600 B (row 1024 = zeros for padding)

// ---------------- static scratch ----------------
__device__ float          g_cur1[(size_t)B_N * H_N];       // 268 MB
__device__ unsigned short g_code[B_N][H_N];                // 134 MB: 10-bit spike codes
__device__ unsigned short g_klist[B_N][2][LISTW];          // 294 MB: sorted k lists
__device__ unsigned short g_goff[B_N][2][32];              // group end-offsets (idx g-1 = end of group g)
__device__ float          g_pp[NSTRIPE][STEPS][B_N];       // 84 MB: per-stripe output partials
__device__ unsigned       g_ticket;

// ---------------- K1: cur1 = x @ W1 + b1 (fp32 SIMT, validated) ----------------
__global__ __launch_bounds__(256) void k1_gemm(const float* __restrict__ X,
                                               const float* __restrict__ W1,
                                               const float* __restrict__ b1) {
    __shared__ float As[16][128];
    __shared__ float Bs[16][128];
    const int tid = threadIdx.x;
    const int tx = tid & 15, ty = tid >> 4;
    const int m0 = blockIdx.y * 128;
    const int n0 = blockIdx.x * 128;

    float acc[8][8];
#pragma unroll
    for (int i = 0; i < 8; i++)
#pragma unroll
        for (int j = 0; j < 8; j++) acc[i][j] = 0.f;

    for (int kc = 0; kc < IN_N; kc += 16) {
        float4 av[2], bv[2];
#pragma unroll
        for (int l = 0; l < 2; l++) {
            int f = tid + l * 256;
            int row = f >> 2, kq = (f & 3) * 4;
            av[l] = *(const float4*)&X[(size_t)(m0 + row) * IN_N + kc + kq];
            int kr = f >> 5, c4 = (f & 31) * 4;
            bv[l] = *(const float4*)&W1[(size_t)(kc + kr) * H_N + n0 + c4];
        }
        __syncthreads();
#pragma unroll
        for (int l = 0; l < 2; l++) {
            int f = tid + l * 256;
            int row = f >> 2, kq = (f & 3) * 4;
            As[kq + 0][row] = av[l].x; As[kq + 1][row] = av[l].y;
            As[kq + 2][row] = av[l].z; As[kq + 3][row] = av[l].w;
            int kr = f >> 5, c4 = (f & 31) * 4;
            *(float4*)&Bs[kr][c4] = bv[l];
        }
        __syncthreads();
#pragma unroll
        for (int kk = 0; kk < 16; kk++) {
            float a[8], bb[8];
            *(float4*)&a[0]  = *(float4*)&As[kk][ty * 8];
            *(float4*)&a[4]  = *(float4*)&As[kk][ty * 8 + 4];
            *(float4*)&bb[0] = *(float4*)&Bs[kk][tx * 8];
            *(float4*)&bb[4] = *(float4*)&Bs[kk][tx * 8 + 4];
#pragma unroll
            for (int i = 0; i < 8; i++)
#pragma unroll
                for (int j = 0; j < 8; j++) acc[i][j] += a[i] * bb[j];
        }
    }

    float bias[8];
#pragma unroll
    for (int j = 0; j < 8; j++) bias[j] = b1[n0 + tx * 8 + j];
#pragma unroll
    for (int i = 0; i < 8; i++) {
        int row = m0 + ty * 8 + i;
        float4 o0, o1;
        o0.x = acc[i][0] + bias[0]; o0.y = acc[i][1] + bias[1];
        o0.z = acc[i][2] + bias[2]; o0.w = acc[i][3] + bias[3];
        o1.x = acc[i][4] + bias[4]; o1.y = acc[i][5] + bias[5];
        o1.z = acc[i][6] + bias[6]; o1.w = acc[i][7] + bias[7];
        *(float4*)&g_cur1[(size_t)row * H_N + n0 + tx * 8]     = o0;
        *(float4*)&g_cur1[(size_t)row * H_N + n0 + tx * 8 + 4] = o1;
    }
}

// ---------------- K2: layer-1 LIF -> 10-bit spike code per (b,k); resets ticket ----------
__global__ __launch_bounds__(256) void k2_codes() {
    if (blockIdx.x == 0 && threadIdx.x == 0) g_ticket = 0;
    const int idx = blockIdx.x * 256 + threadIdx.x;     // over B*H
    const int b = idx >> 10, k = idx & (H_N - 1);
    const float c = g_cur1[(size_t)b * H_N + k];
    float m = 0.f;
    unsigned code = 0;
#pragma unroll
    for (int t = 0; t < STEPS; t++) {
        float r = (m > THR) ? THR : 0.f;
        m = BETA * m + c - r;
        code |= (m > THR) ? (1u << t) : 0u;
    }
    g_code[b][k] = (unsigned short)code;
}

// ---------------- K2b: deterministic per-(b,half) counting sort into 32 groups ----------
// warp per b; groups 4-aligned, padded with k=1024 (zero row); group 0 excluded.
__global__ __launch_bounds__(256) void k2b_sort() {
    __shared__ unsigned scnt[8][32];
    const int wid  = threadIdx.x >> 5;
    const int lane = threadIdx.x & 31;
    const int b    = blockIdx.x * 8 + wid;
    const unsigned short* codes = g_code[b];
    const unsigned ltmask = (1u << lane) - 1u;

    for (int h = 0; h < 2; h++) {
        unsigned* cnt = scnt[wid];
        cnt[lane] = 0;
        __syncwarp();
        // pass 1: counts (deterministic, leader-writes)
        for (int it = 0; it < 32; it++) {
            unsigned c = codes[it * 32 + lane];
            unsigned g = (h ? (c >> 5) : c) & 31u;
            unsigned mm = __match_any_sync(0xFFFFFFFFu, g);
            if (g != 0 && (__ffs(mm) - 1) == lane) cnt[g] += __popc(mm);
            __syncwarp();
        }
        unsigned cg  = (lane > 0) ? cnt[lane] : 0u;
        unsigned pad = (cg + 3u) & ~3u;
        // inclusive scan of pad across lanes -> group ends
        unsigned s = pad;
#pragma unroll
        for (int off = 1; off < 32; off <<= 1) {
            unsigned n = __shfl_up_sync(0xFFFFFFFFu, s, off);
            if (lane >= off) s += n;
        }
        if (lane >= 1) g_goff[b][h][lane - 1] = (unsigned short)s;
        if (lane == 0) g_goff[b][h][31] = 0;
        cnt[lane] = s - pad;                      // cursor = start
        __syncwarp();
        // pass 2: deterministic scatter
        for (int it = 0; it < 32; it++) {
            unsigned c = codes[it * 32 + lane];
            unsigned g = (h ? (c >> 5) : c) & 31u;
            unsigned mm = __match_any_sync(0xFFFFFFFFu, g);
            unsigned rank = __popc(mm & ltmask);
            unsigned pos0 = cnt[g];               // broadcast read
            __syncwarp();
            if (g != 0) g_klist[b][h][pos0 + rank] = (unsigned short)(it * 32 + lane);
            if (g != 0 && (__ffs(mm) - 1) == lane) cnt[g] = pos0 + __popc(mm);
            __syncwarp();
        }
        // pad fill to 4-alignment with dummy k=1024
        if (lane >= 1) {
            for (unsigned p = cnt[lane]; p < s; p++)
                g_klist[b][h][p] = 1024;
        }
        __syncwarp();
    }
}

// ---------------- K3g: group-sum GEMM + fused layer-2 LIF + output projection ----------
// Persistent CTAs, ticket tasks: task = (stripe of 32 cols, chunk of 256 b).
// W2 stripe resident in smem; warp handles 32 b's; lane = one column.
__global__ __launch_bounds__(256, 1) void k3g(const float* __restrict__ W2,
                                              const float* __restrict__ b2,
                                              const float* __restrict__ Wo) {
    extern __shared__ float sW[];                 // [1025][SWPITCH]
    __shared__ unsigned sTask;
    const int tid  = threadIdx.x;
    const int lane = tid & 31, wid = tid >> 5;

    if (tid < 32) sW[1024 * SWPITCH + tid] = 0.f; // dummy row for padding entries
    __syncthreads();

    for (;;) {
        if (tid == 0) sTask = atomicAdd(&g_ticket, 1u);
        __syncthreads();
        const unsigned task = sTask;
        __syncthreads();
        if (task >= NTASK) break;
        const int stripe = task & (NSTRIPE - 1);
        const int chunk  = task >> 5;
        const int n0     = stripe * 32;

        // stage W2 stripe: 1024 rows x 32 cols
        for (int i = tid; i < 1024 * 8; i += 256) {
            int k = i >> 3, q = i & 7;
            float4 v = *(const float4*)&W2[(size_t)k * H_N + n0 + q * 4];
            float* d = &sW[k * SWPITCH + q * 4];
            d[0] = v.x; d[1] = v.y; d[2] = v.z; d[3] = v.w;
        }
        __syncthreads();

        const float b2c = b2[n0 + lane];
        const float woc = Wo[n0 + lane];

        for (int bi = 0; bi < 32; bi++) {
            const int b = chunk * 256 + wid * 32 + bi;
            float m2 = 0.f;
#pragma unroll
            for (int h = 0; h < 2; h++) {
                const unsigned short* L = g_klist[b][h];
                int ends = (int)g_goff[b][h][lane];          // lane g-1 -> end of group g
                int total = __shfl_sync(0xFFFFFFFFu, ends, 30);
                float S[5] = {0.f, 0.f, 0.f, 0.f, 0.f};
                int ptr = 0, g = 0;
                int end_cur = __shfl_sync(0xFFFFFFFFu, ends, 0);
                unsigned win = L[lane];
                int wb = 0;
                while (ptr < total) {
                    while (end_cur <= ptr) {
                        ++g;
                        end_cur = __shfl_sync(0xFFFFFFFFu, ends, g);
                    }
                    float G = 0.f;
                    for (; ptr < end_cur; ptr += 4) {
                        if ((ptr & 31) == 0 && ptr != wb) {
                            wb = ptr;
                            win = L[wb + lane];
                        }
                        int o = ptr - wb;
                        int k0 = __shfl_sync(0xFFFFFFFFu, win, o);
                        int k1 = __shfl_sync(0xFFFFFFFFu, win, o + 1);
                        int k2 = __shfl_sync(0xFFFFFFFFu, win, o + 2);
                        int k3 = __shfl_sync(0xFFFFFFFFu, win, o + 3);
                        G += sW[k0 * SWPITCH + lane];
                        G += sW[k1 * SWPITCH + lane];
                        G += sW[k2 * SWPITCH + lane];
                        G += sW[k3 * SWPITCH + lane];
                    }
                    int grp = g + 1;
#pragma unroll
                    for (int t = 0; t < 5; t++)
                        if ((grp >> t) & 1) S[t] += G;
                }
                // 5 LIF steps of this half (cols local; reduce s2*Wo across lanes)
#pragma unroll
                for (int j = 0; j < 5; j++) {
                    float cur = S[j] + b2c;
                    float r = (m2 > THR) ? THR : 0.f;
                    m2 = BETA * m2 + cur - r;
                    float v = (m2 > THR) ? woc : 0.f;
#pragma unroll
                    for (int off = 16; off; off >>= 1)
                        v += __shfl_down_sync(0xFFFFFFFFu, v, off);
                    if (lane == 0) g_pp[stripe][h * 5 + j][b] = v;
                }
            }
        }
        __syncthreads();   // all warps done before next task overwrites sW
    }
}

// ---------------- K5: deterministic stripe reduce + output LIF + mean ----------------
__global__ __launch_bounds__(256) void k5_out(const float* __restrict__ bo,
                                              float* __restrict__ out) {
    const int b = blockIdx.x * 256 + threadIdx.x;
    const float bo0 = bo[0];
    float mo = 0.f, acc = 0.f;
#pragma unroll
    for (int t = 0; t < STEPS; t++) {
        float tot = bo0;
#pragma unroll
        for (int s = 0; s < NSTRIPE; s++) tot += g_pp[s][t][b];
        float r = (mo > THR) ? THR : 0.f;
        mo = BETA * mo + tot - r;
        acc += mo;
    }
    out[b] = acc * (1.f / STEPS);
}

// ---------------- launcher ----------------
extern "C" void kernel_launch(void* const* d_in, const int* in_sizes, int n_in,
                              void* d_out, int out_size) {
    const float* x  = (const float*)d_in[0];
    const float* W1 = (const float*)d_in[1];
    const float* b1 = (const float*)d_in[2];
    const float* W2 = (const float*)d_in[3];
    const float* b2 = (const float*)d_in[4];
    const float* Wo = (const float*)d_in[5];
    const float* bo = (const float*)d_in[6];
    float* out = (float*)d_out;

    cudaFuncSetAttribute(k3g, cudaFuncAttributeMaxDynamicSharedMemorySize, SMEMB);

    k1_gemm<<<dim3(H_N / 128, B_N / 128), 256>>>(x, W1, b1);
    k2_codes<<<(B_N * H_N) / 256, 256>>>();
    k2b_sort<<<B_N / 8, 256>>>();
    k3g<<<148, 256, SMEMB>>>(W2, b2, Wo);
    k5_out<<<B_N / 256, 256>>>(bo, out);
}

// round 6
// speedup vs baseline: 2.2052x; 2.2052x over previous
#include <cuda_runtime.h>
#include <cstdint>

#define B_N   65536
#define IN_N  512
#define H_N   1024
#define STEPS 10
#define BETA  0.9f
#define THR   1.0f

#define NSTRIPE 32                     // 1024 cols / 32
#define LISTW   1128                   // padded list length per (b,half) + prefetch margin
#define CHUNKB  512                    // b's per task (16 warps x 32)
#define NCHUNK  (B_N / CHUNKB)         // 128
#define NTASK   (NSTRIPE * NCHUNK)     // 4096
#define SMEMB   (1025 * 32 * 4)        // 131200 B (row 1024 = zeros for dummies)

// ---------------- static scratch ----------------
__device__ float          g_cur1[(size_t)B_N * H_N];       // 268 MB
__device__ unsigned short g_code[B_N][H_N];                // 134 MB: layer-1 10-bit spike codes
__device__ unsigned       g_klist[B_N][2][LISTW];          // 591 MB: sorted lists of k*128 (byte offsets)
__device__ unsigned short g_goff[B_N][2][32];              // padded group end-offsets
__device__ unsigned short g_s2code[B_N][H_N];              // 134 MB: layer-2 10-bit spike codes
__device__ unsigned       g_ticket;

// ---------------- K1: cur1 = x @ W1 + b1 (fp32 SIMT, validated) ----------------
__global__ __launch_bounds__(256) void k1_gemm(const float* __restrict__ X,
                                               const float* __restrict__ W1,
                                               const float* __restrict__ b1) {
    __shared__ float As[16][128];
    __shared__ float Bs[16][128];
    const int tid = threadIdx.x;
    const int tx = tid & 15, ty = tid >> 4;
    const int m0 = blockIdx.y * 128;
    const int n0 = blockIdx.x * 128;

    float acc[8][8];
#pragma unroll
    for (int i = 0; i < 8; i++)
#pragma unroll
        for (int j = 0; j < 8; j++) acc[i][j] = 0.f;

    for (int kc = 0; kc < IN_N; kc += 16) {
        float4 av[2], bv[2];
#pragma unroll
        for (int l = 0; l < 2; l++) {
            int f = tid + l * 256;
            int row = f >> 2, kq = (f & 3) * 4;
            av[l] = *(const float4*)&X[(size_t)(m0 + row) * IN_N + kc + kq];
            int kr = f >> 5, c4 = (f & 31) * 4;
            bv[l] = *(const float4*)&W1[(size_t)(kc + kr) * H_N + n0 + c4];
        }
        __syncthreads();
#pragma unroll
        for (int l = 0; l < 2; l++) {
            int f = tid + l * 256;
            int row = f >> 2, kq = (f & 3) * 4;
            As[kq + 0][row] = av[l].x; As[kq + 1][row] = av[l].y;
            As[kq + 2][row] = av[l].z; As[kq + 3][row] = av[l].w;
            int kr = f >> 5, c4 = (f & 31) * 4;
            *(float4*)&Bs[kr][c4] = bv[l];
        }
        __syncthreads();
#pragma unroll
        for (int kk = 0; kk < 16; kk++) {
            float a[8], bb[8];
            *(float4*)&a[0]  = *(float4*)&As[kk][ty * 8];
            *(float4*)&a[4]  = *(float4*)&As[kk][ty * 8 + 4];
            *(float4*)&bb[0] = *(float4*)&Bs[kk][tx * 8];
            *(float4*)&bb[4] = *(float4*)&Bs[kk][tx * 8 + 4];
#pragma unroll
            for (int i = 0; i < 8; i++)
#pragma unroll
                for (int j = 0; j < 8; j++) acc[i][j] += a[i] * bb[j];
        }
    }

    float bias[8];
#pragma unroll
    for (int j = 0; j < 8; j++) bias[j] = b1[n0 + tx * 8 + j];
#pragma unroll
    for (int i = 0; i < 8; i++) {
        int row = m0 + ty * 8 + i;
        float4 o0, o1;
        o0.x = acc[i][0] + bias[0]; o0.y = acc[i][1] + bias[1];
        o0.z = acc[i][2] + bias[2]; o0.w = acc[i][3] + bias[3];
        o1.x = acc[i][4] + bias[4]; o1.y = acc[i][5] + bias[5];
        o1.z = acc[i][6] + bias[6]; o1.w = acc[i][7] + bias[7];
        *(float4*)&g_cur1[(size_t)row * H_N + n0 + tx * 8]     = o0;
        *(float4*)&g_cur1[(size_t)row * H_N + n0 + tx * 8 + 4] = o1;
    }
}

// ---------------- K2: layer-1 LIF -> 10-bit spike code per (b,k); resets ticket ----------
__global__ __launch_bounds__(256) void k2_codes() {
    if (blockIdx.x == 0 && threadIdx.x == 0) g_ticket = 0;
    const int idx = blockIdx.x * 256 + threadIdx.x;
    const int b = idx >> 10, k = idx & (H_N - 1);
    const float c = g_cur1[(size_t)b * H_N + k];
    float m = 0.f;
    unsigned code = 0;
#pragma unroll
    for (int t = 0; t < STEPS; t++) {
        float r = (m > THR) ? THR : 0.f;
        m = BETA * m + c - r;
        code |= (m > THR) ? (1u << t) : 0u;
    }
    g_code[b][k] = (unsigned short)code;
}

// ---------------- K2b: deterministic per-(b,half) counting sort into 32 groups ----------
// warp per b; groups 4-aligned, padded with dummy offset (zero row 1024); group 0 excluded.
__global__ __launch_bounds__(256) void k2b_sort() {
    __shared__ unsigned scnt[8][32];
    const int wid  = threadIdx.x >> 5;
    const int lane = threadIdx.x & 31;
    const int b    = blockIdx.x * 8 + wid;
    const unsigned short* codes = g_code[b];
    const unsigned ltmask = (1u << lane) - 1u;
    const unsigned DUMMY = 1024u * 128u;

    for (int h = 0; h < 2; h++) {
        unsigned* cnt = scnt[wid];
        cnt[lane] = 0;
        __syncwarp();
        // pass 1: counts
        for (int it = 0; it < 32; it++) {
            unsigned c = codes[it * 32 + lane];
            unsigned g = (h ? (c >> 5) : c) & 31u;
            unsigned mm = __match_any_sync(0xFFFFFFFFu, g);
            if (g != 0 && (__ffs(mm) - 1) == lane) cnt[g] += __popc(mm);
            __syncwarp();
        }
        unsigned cg  = (lane > 0) ? cnt[lane] : 0u;
        unsigned pad = (cg + 3u) & ~3u;
        unsigned s = pad;
#pragma unroll
        for (int off = 1; off < 32; off <<= 1) {
            unsigned n = __shfl_up_sync(0xFFFFFFFFu, s, off);
            if (lane >= off) s += n;
        }
        if (lane >= 1) g_goff[b][h][lane - 1] = (unsigned short)s;
        if (lane == 0) g_goff[b][h][31] = 0;
        cnt[lane] = s - pad;                      // cursor = start of group `lane`
        __syncwarp();
        // pass 2: deterministic scatter of byte offsets k*128
        for (int it = 0; it < 32; it++) {
            unsigned c = codes[it * 32 + lane];
            unsigned g = (h ? (c >> 5) : c) & 31u;
            unsigned mm = __match_any_sync(0xFFFFFFFFu, g);
            unsigned rank = __popc(mm & ltmask);
            unsigned pos0 = cnt[g];
            __syncwarp();
            if (g != 0) g_klist[b][h][pos0 + rank] = (unsigned)(it * 32 + lane) * 128u;
            if (g != 0 && (__ffs(mm) - 1) == lane) cnt[g] = pos0 + __popc(mm);
            __syncwarp();
        }
        // pad fill to 4-alignment with dummy (zero-row offset)
        if (lane >= 1) {
            for (unsigned p = cnt[lane]; p < s; p++)
                g_klist[b][h][p] = DUMMY;
        }
        __syncwarp();
    }
}

// ---------------- K3g: group-sum GEMM + fused layer-2 LIF -> s2 spike codes ----------
// Persistent CTAs (512 thr = 16 warps). Task = (stripe of 32 cols, chunk of 512 b).
// W2 stripe resident in smem (pitch 32, conflict-free since k is warp-uniform).
// Inner loop: broadcast uint4 list prefetch + LDS/FADD stream, no shfl per k.
__global__ __launch_bounds__(512, 1) void k3g(const float* __restrict__ W2,
                                              const float* __restrict__ b2) {
    extern __shared__ char smem[];
    __shared__ unsigned sTask;
    const int tid  = threadIdx.x;
    const int lane = tid & 31, wid = tid >> 5;
    const unsigned laneB = lane * 4;

    // zero dummy row 1024 (persists across tasks)
    if (tid < 32) *(float*)(smem + 1024 * 128 + tid * 4) = 0.f;
    __syncthreads();

    for (;;) {
        if (tid == 0) sTask = atomicAdd(&g_ticket, 1u);
        __syncthreads();
        const unsigned task = sTask;
        __syncthreads();
        if (task >= NTASK) break;
        const int stripe = task & (NSTRIPE - 1);     // 32 consecutive tasks share a chunk
        const int chunk  = task >> 5;
        const int n0     = stripe * 32;

        // stage W2 stripe: 1024 rows x 32 cols (float4 per thread-slot)
        for (int i = tid; i < 1024 * 8; i += 512) {
            int k = i >> 3, q = i & 7;
            *(float4*)(smem + k * 128 + q * 16) =
                *(const float4*)&W2[(size_t)k * H_N + n0 + q * 4];
        }
        __syncthreads();

        const float b2c = b2[n0 + lane];

        for (int bi = 0; bi < 32; bi++) {
            const int b = chunk * CHUNKB + wid * 32 + bi;
            float m2 = 0.f;
            unsigned code = 0;
#pragma unroll
            for (int h = 0; h < 2; h++) {
                const unsigned* L = g_klist[b][h];
                int ends  = (int)g_goff[b][h][lane];
                int total = __shfl_sync(0xFFFFFFFFu, ends, 30);
                float S[5] = {0.f, 0.f, 0.f, 0.f, 0.f};
                int ptr = 0, g = 0;
                int end_cur = __shfl_sync(0xFFFFFFFFu, ends, 0);
                uint4 kk = *(const uint4*)L;          // prefetched window (valid if total>0)
                while (ptr < total) {
                    while (end_cur <= ptr) {
                        ++g;
                        end_cur = __shfl_sync(0xFFFFFFFFu, ends, g);
                    }
                    float G0 = 0.f, G1 = 0.f;
                    for (; ptr < end_cur; ptr += 4) {
                        uint4 nx = *(const uint4*)&L[ptr + 4];
                        G0 += *(const float*)(smem + kk.x + laneB);
                        G1 += *(const float*)(smem + kk.y + laneB);
                        G0 += *(const float*)(smem + kk.z + laneB);
                        G1 += *(const float*)(smem + kk.w + laneB);
                        kk = nx;
                    }
                    float G = G0 + G1;
                    int grp = g + 1;
                    if (grp & 1)  S[0] += G;
                    if (grp & 2)  S[1] += G;
                    if (grp & 4)  S[2] += G;
                    if (grp & 8)  S[3] += G;
                    if (grp & 16) S[4] += G;
                }
                // 5 LIF steps of this half; collect spike bits
#pragma unroll
                for (int j = 0; j < 5; j++) {
                    float cur = S[j] + b2c;
                    float r = (m2 > THR) ? THR : 0.f;
                    m2 = BETA * m2 + cur - r;
                    if (m2 > THR) code |= 1u << (h * 5 + j);
                }
            }
            g_s2code[b][n0 + lane] = (unsigned short)code;
        }
        __syncthreads();   // all warps done before next task overwrites smem
    }
}

// ---------------- K5: s2 codes -> Wo subset-sums, output LIF, mean ----------------
__global__ __launch_bounds__(256) void k5_out(const float* __restrict__ Wo,
                                              const float* __restrict__ bo,
                                              float* __restrict__ out) {
    __shared__ float sWo[H_N];
    for (int i = threadIdx.x; i < H_N; i += 256) sWo[i] = Wo[i];
    __syncthreads();
    const int wid = threadIdx.x >> 5, lane = threadIdx.x & 31;
    const int b = blockIdx.x * 8 + wid;

    float S[STEPS];
#pragma unroll
    for (int t = 0; t < STEPS; t++) S[t] = 0.f;

    for (int j = 0; j < 32; j++) {
        unsigned code = g_s2code[b][j * 32 + lane];
        float w = sWo[j * 32 + lane];
#pragma unroll
        for (int t = 0; t < STEPS; t++)
            S[t] += ((code >> t) & 1u) ? w : 0.f;
    }
#pragma unroll
    for (int t = 0; t < STEPS; t++)
#pragma unroll
        for (int off = 16; off; off >>= 1)
            S[t] += __shfl_down_sync(0xFFFFFFFFu, S[t], off);

    if (lane == 0) {
        const float bo0 = bo[0];
        float mo = 0.f, acc = 0.f;
#pragma unroll
        for (int t = 0; t < STEPS; t++) {
            float tot = S[t] + bo0;
            float r = (mo > THR) ? THR : 0.f;
            mo = BETA * mo + tot - r;
            acc += mo;
        }
        out[b] = acc * (1.f / STEPS);
    }
}

// ---------------- launcher ----------------
extern "C" void kernel_launch(void* const* d_in, const int* in_sizes, int n_in,
                              void* d_out, int out_size) {
    const float* x  = (const float*)d_in[0];
    const float* W1 = (const float*)d_in[1];
    const float* b1 = (const float*)d_in[2];
    const float* W2 = (const float*)d_in[3];
    const float* b2 = (const float*)d_in[4];
    const float* Wo = (const float*)d_in[5];
    const float* bo = (const float*)d_in[6];
    float* out = (float*)d_out;

    cudaFuncSetAttribute(k3g, cudaFuncAttributeMaxDynamicSharedMemorySize, SMEMB);

    k1_gemm<<<dim3(H_N / 128, B_N / 128), 256>>>(x, W1, b1);
    k2_codes<<<(B_N * H_N) / 256, 256>>>();
    k2b_sort<<<B_N / 8, 256>>>();
    k3g<<<148, 512, SMEMB>>>(W2, b2);
    k5_out<<<B_N / 8, 256>>>(Wo, bo, out);
}

// round 7
// speedup vs baseline: 2.6136x; 1.1852x over previous
#include <cuda_runtime.h>
#include <cstdint>

#define B_N   65536
#define IN_N  512
#define H_N   1024
#define STEPS 10
#define BETA  0.9f
#define THR   1.0f

#define NSTRIPE 16                     // 1024 cols / 64
#define CHUNKB  32                     // b's per task (16 warps x 2)
#define NCHUNK  (B_N / CHUNKB)         // 2048
#define NTASK   (NSTRIPE * NCHUNK)     // 32768
#define LISTW2  648                    // padded sub-list length (512 + 124 pad + margin)

// smem layout for k3g
#define SM_W2    0                     // 512 rows x 256B = 131072
#define SM_DUMMY 131072                // 256B zero row (offset 131072 = dummy)
#define SM_SCR   131584                // 32 b x 10 x 32 lanes x 8B = 81920
#define SMEMB    (131584 + 81920)      // 213504

// ---------------- static scratch ----------------
__device__ float          g_cur1[(size_t)B_N * H_N];       // 268 MB
__device__ unsigned short g_code[B_N][H_N];                // 134 MB: layer-1 10-bit spike codes
__device__ unsigned       g_klist[B_N][2][2][LISTW2];      // 680 MB: [b][thalf][khalf] offsets klocal*256
__device__ unsigned short g_goff[B_N][2][2][32];           // padded group end-offsets
__device__ unsigned short g_s2code[B_N][H_N];              // 134 MB: layer-2 10-bit spike codes
__device__ unsigned       g_ticket;

// ---------------- K1: cur1 = x @ W1 + b1 (fp32 SIMT, validated) ----------------
__global__ __launch_bounds__(256) void k1_gemm(const float* __restrict__ X,
                                               const float* __restrict__ W1,
                                               const float* __restrict__ b1) {
    __shared__ float As[16][128];
    __shared__ float Bs[16][128];
    const int tid = threadIdx.x;
    const int tx = tid & 15, ty = tid >> 4;
    const int m0 = blockIdx.y * 128;
    const int n0 = blockIdx.x * 128;

    float acc[8][8];
#pragma unroll
    for (int i = 0; i < 8; i++)
#pragma unroll
        for (int j = 0; j < 8; j++) acc[i][j] = 0.f;

    for (int kc = 0; kc < IN_N; kc += 16) {
        float4 av[2], bv[2];
#pragma unroll
        for (int l = 0; l < 2; l++) {
            int f = tid + l * 256;
            int row = f >> 2, kq = (f & 3) * 4;
            av[l] = *(const float4*)&X[(size_t)(m0 + row) * IN_N + kc + kq];
            int kr = f >> 5, c4 = (f & 31) * 4;
            bv[l] = *(const float4*)&W1[(size_t)(kc + kr) * H_N + n0 + c4];
        }
        __syncthreads();
#pragma unroll
        for (int l = 0; l < 2; l++) {
            int f = tid + l * 256;
            int row = f >> 2, kq = (f & 3) * 4;
            As[kq + 0][row] = av[l].x; As[kq + 1][row] = av[l].y;
            As[kq + 2][row] = av[l].z; As[kq + 3][row] = av[l].w;
            int kr = f >> 5, c4 = (f & 31) * 4;
            *(float4*)&Bs[kr][c4] = bv[l];
        }
        __syncthreads();
#pragma unroll
        for (int kk = 0; kk < 16; kk++) {
            float a[8], bb[8];
            *(float4*)&a[0]  = *(float4*)&As[kk][ty * 8];
            *(float4*)&a[4]  = *(float4*)&As[kk][ty * 8 + 4];
            *(float4*)&bb[0] = *(float4*)&Bs[kk][tx * 8];
            *(float4*)&bb[4] = *(float4*)&Bs[kk][tx * 8 + 4];
#pragma unroll
            for (int i = 0; i < 8; i++)
#pragma unroll
                for (int j = 0; j < 8; j++) acc[i][j] += a[i] * bb[j];
        }
    }

    float bias[8];
#pragma unroll
    for (int j = 0; j < 8; j++) bias[j] = b1[n0 + tx * 8 + j];
#pragma unroll
    for (int i = 0; i < 8; i++) {
        int row = m0 + ty * 8 + i;
        float4 o0, o1;
        o0.x = acc[i][0] + bias[0]; o0.y = acc[i][1] + bias[1];
        o0.z = acc[i][2] + bias[2]; o0.w = acc[i][3] + bias[3];
        o1.x = acc[i][4] + bias[4]; o1.y = acc[i][5] + bias[5];
        o1.z = acc[i][6] + bias[6]; o1.w = acc[i][7] + bias[7];
        *(float4*)&g_cur1[(size_t)row * H_N + n0 + tx * 8]     = o0;
        *(float4*)&g_cur1[(size_t)row * H_N + n0 + tx * 8 + 4] = o1;
    }
}

// ---------------- K2: layer-1 LIF -> 10-bit spike code per (b,k); resets ticket ----------
__global__ __launch_bounds__(256) void k2_codes() {
    if (blockIdx.x == 0 && threadIdx.x == 0) g_ticket = 0;
    const int idx = blockIdx.x * 256 + threadIdx.x;
    const int b = idx >> 10, k = idx & (H_N - 1);
    const float c = g_cur1[(size_t)b * H_N + k];
    float m = 0.f;
    unsigned code = 0;
#pragma unroll
    for (int t = 0; t < STEPS; t++) {
        float r = (m > THR) ? THR : 0.f;
        m = BETA * m + c - r;
        code |= (m > THR) ? (1u << t) : 0u;
    }
    g_code[b][k] = (unsigned short)code;
}

// ---------------- K2b: per-(b, thalf, khalf) counting sort into 32 groups --------------
// warp per b; groups 4-aligned, padded with dummy offset (zero row). Group 0 excluded.
// Entries are byte offsets klocal*256 (256B smem row pitch, 64 cols).
__global__ __launch_bounds__(256) void k2b_sort() {
    __shared__ unsigned scnt[8][32];
    const int wid  = threadIdx.x >> 5;
    const int lane = threadIdx.x & 31;
    const int b    = blockIdx.x * 8 + wid;
    const unsigned short* codes = g_code[b];
    const unsigned ltmask = (1u << lane) - 1u;
    const unsigned DUMMY = 131072u;            // zero row

    for (int h = 0; h < 2; h++) {
        for (int kh = 0; kh < 2; kh++) {
            unsigned* cnt = scnt[wid];
            cnt[lane] = 0;
            __syncwarp();
            // pass 1: counts
            for (int it = 0; it < 16; it++) {
                unsigned c = codes[kh * 512 + it * 32 + lane];
                unsigned g = (h ? (c >> 5) : c) & 31u;
                unsigned mm = __match_any_sync(0xFFFFFFFFu, g);
                if (g != 0 && (__ffs(mm) - 1) == lane) cnt[g] += __popc(mm);
                __syncwarp();
            }
            unsigned cg  = (lane > 0) ? cnt[lane] : 0u;
            unsigned pad = (cg + 3u) & ~3u;
            unsigned s = pad;
#pragma unroll
            for (int off = 1; off < 32; off <<= 1) {
                unsigned n = __shfl_up_sync(0xFFFFFFFFu, s, off);
                if (lane >= off) s += n;
            }
            if (lane >= 1) g_goff[b][h][kh][lane - 1] = (unsigned short)s;
            if (lane == 0) g_goff[b][h][kh][31] = 0;
            cnt[lane] = s - pad;               // cursor = start of group `lane`
            __syncwarp();
            // pass 2: deterministic scatter
            for (int it = 0; it < 16; it++) {
                unsigned c = codes[kh * 512 + it * 32 + lane];
                unsigned g = (h ? (c >> 5) : c) & 31u;
                unsigned mm = __match_any_sync(0xFFFFFFFFu, g);
                unsigned rank = __popc(mm & ltmask);
                unsigned pos0 = cnt[g];
                __syncwarp();
                if (g != 0) g_klist[b][h][kh][pos0 + rank] = (unsigned)(it * 32 + lane) * 256u;
                if (g != 0 && (__ffs(mm) - 1) == lane) cnt[g] = pos0 + __popc(mm);
                __syncwarp();
            }
            // pad fill to 4-alignment with dummy
            if (lane >= 1) {
                for (unsigned p = cnt[lane]; p < s; p++)
                    g_klist[b][h][kh][p] = DUMMY;
            }
            __syncwarp();
        }
    }
}

// ---------------- K3g: 64-col group-sum GEMM + fused layer-2 LIF -> s2 codes ----------
// Persistent CTAs (512 thr). Task = (stripe of 64 cols, chunk of 32 b); warp owns 2 b's.
// Lane covers 2 cols (LDS.64). W2 staged per k-half (512 rows x 256B); per-(b,col)
// step-sums persist across k-phases in smem scratch.
__global__ __launch_bounds__(512, 1) void k3g(const float* __restrict__ W2,
                                              const float* __restrict__ b2) {
    extern __shared__ char smem[];
    __shared__ unsigned sTask;
    const int tid  = threadIdx.x;
    const int lane = tid & 31, wid = tid >> 5;
    const unsigned laneB = lane * 8;

    if (tid < 32) *(unsigned long long*)(smem + SM_DUMMY + tid * 8) = 0ull;
    __syncthreads();

    for (;;) {
        if (tid == 0) sTask = atomicAdd(&g_ticket, 1u);
        __syncthreads();
        const unsigned task = sTask;
        __syncthreads();
        if (task >= NTASK) break;
        const int stripe = task & (NSTRIPE - 1);   // consecutive tasks share a chunk
        const int chunk  = task >> 4;
        const int n0     = stripe * 64;
        const int b0     = chunk * CHUNKB + wid * 2;
        const float2 b2v = *(const float2*)&b2[n0 + lane * 2];

        float2 m2[2];
        unsigned codeo[2];

        for (int kh = 0; kh < 2; kh++) {
            __syncthreads();                       // walks of previous phase done
            // stage rows [kh*512, +512) x 64 cols
            for (int i = tid; i < 512 * 16; i += 512) {
                int k = i >> 4, q = i & 15;
                *(float4*)(smem + k * 256 + q * 16) =
                    *(const float4*)&W2[(size_t)(kh * 512 + k) * H_N + n0 + q * 4];
            }
            __syncthreads();

#pragma unroll
            for (int bs = 0; bs < 2; bs++) {
                const int b = b0 + bs;
                if (kh == 1) { m2[bs] = make_float2(0.f, 0.f); codeo[bs] = 0u; }
#pragma unroll
                for (int h = 0; h < 2; h++) {
                    const unsigned* L = g_klist[b][h][kh];
                    int ends  = (int)g_goff[b][h][kh][lane];
                    int total = __shfl_sync(0xFFFFFFFFu, ends, 30);
                    float2 S[5];
#pragma unroll
                    for (int j = 0; j < 5; j++) S[j] = make_float2(0.f, 0.f);
                    int ptr = 0, g = 0;
                    int end_cur = __shfl_sync(0xFFFFFFFFu, ends, 0);
                    uint4 kk = *(const uint4*)L;
                    while (ptr < total) {
                        while (end_cur <= ptr) {
                            ++g;
                            end_cur = __shfl_sync(0xFFFFFFFFu, ends, g);
                        }
                        float2 G0 = make_float2(0.f, 0.f), G1 = make_float2(0.f, 0.f);
                        for (; ptr < end_cur; ptr += 4) {
                            uint4 nx = *(const uint4*)&L[ptr + 4];
                            float2 v0 = *(const float2*)(smem + kk.x + laneB);
                            float2 v1 = *(const float2*)(smem + kk.y + laneB);
                            float2 v2 = *(const float2*)(smem + kk.z + laneB);
                            float2 v3 = *(const float2*)(smem + kk.w + laneB);
                            G0.x += v0.x; G0.y += v0.y;
                            G1.x += v1.x; G1.y += v1.y;
                            G0.x += v2.x; G0.y += v2.y;
                            G1.x += v3.x; G1.y += v3.y;
                            kk = nx;
                        }
                        float2 G = make_float2(G0.x + G1.x, G0.y + G1.y);
                        int grp = g + 1;
                        if (grp & 1)  { S[0].x += G.x; S[0].y += G.y; }
                        if (grp & 2)  { S[1].x += G.x; S[1].y += G.y; }
                        if (grp & 4)  { S[2].x += G.x; S[2].y += G.y; }
                        if (grp & 8)  { S[3].x += G.x; S[3].y += G.y; }
                        if (grp & 16) { S[4].x += G.x; S[4].y += G.y; }
                    }
                    const int bl = wid * 2 + bs;
                    char* scr = smem + SM_SCR + (((bl * 10 + h * 5) * 32 + lane) * 8);
                    if (kh == 0) {
#pragma unroll
                        for (int j = 0; j < 5; j++)
                            *(float2*)(scr + j * 256) = S[j];
                    } else {
#pragma unroll
                        for (int j = 0; j < 5; j++) {
                            float2 p = *(const float2*)(scr + j * 256);
                            S[j].x += p.x; S[j].y += p.y;
                        }
                        // 5 LIF steps of this temporal half
#pragma unroll
                        for (int j = 0; j < 5; j++) {
                            float cx = S[j].x + b2v.x;
                            float cy = S[j].y + b2v.y;
                            float rx = (m2[bs].x > THR) ? THR : 0.f;
                            float ry = (m2[bs].y > THR) ? THR : 0.f;
                            m2[bs].x = BETA * m2[bs].x + cx - rx;
                            m2[bs].y = BETA * m2[bs].y + cy - ry;
                            int bit = h * 5 + j;
                            if (m2[bs].x > THR) codeo[bs] |= 1u << bit;
                            if (m2[bs].y > THR) codeo[bs] |= 1u << (16 + bit);
                        }
                    }
                }
                if (kh == 1)
                    *(unsigned*)&g_s2code[b][n0 + lane * 2] = codeo[bs];
            }
        }
        __syncthreads();   // all warps done before next task restages
    }
}

// ---------------- K5: s2 codes -> Wo subset-sums, output LIF, mean ----------------
__global__ __launch_bounds__(256) void k5_out(const float* __restrict__ Wo,
                                              const float* __restrict__ bo,
                                              float* __restrict__ out) {
    __shared__ float sWo[H_N];
    for (int i = threadIdx.x; i < H_N; i += 256) sWo[i] = Wo[i];
    __syncthreads();
    const int wid = threadIdx.x >> 5, lane = threadIdx.x & 31;
    const int b = blockIdx.x * 8 + wid;

    float S[STEPS];
#pragma unroll
    for (int t = 0; t < STEPS; t++) S[t] = 0.f;

    for (int j = 0; j < 32; j++) {
        unsigned code = g_s2code[b][j * 32 + lane];
        float w = sWo[j * 32 + lane];
#pragma unroll
        for (int t = 0; t < STEPS; t++)
            S[t] += ((code >> t) & 1u) ? w : 0.f;
    }
#pragma unroll
    for (int t = 0; t < STEPS; t++)
#pragma unroll
        for (int off = 16; off; off >>= 1)
            S[t] += __shfl_down_sync(0xFFFFFFFFu, S[t], off);

    if (lane == 0) {
        const float bo0 = bo[0];
        float mo = 0.f, acc = 0.f;
#pragma unroll
        for (int t = 0; t < STEPS; t++) {
            float tot = S[t] + bo0;
            float r = (mo > THR) ? THR : 0.f;
            mo = BETA * mo + tot - r;
            acc += mo;
        }
        out[b] = acc * (1.f / STEPS);
    }
}

// ---------------- launcher ----------------
extern "C" void kernel_launch(void* const* d_in, const int* in_sizes, int n_in,
                              void* d_out, int out_size) {
    const float* x  = (const float*)d_in[0];
    const float* W1 = (const float*)d_in[1];
    const float* b1 = (const float*)d_in[2];
    const float* W2 = (const float*)d_in[3];
    const float* b2 = (const float*)d_in[4];
    const float* Wo = (const float*)d_in[5];
    const float* bo = (const float*)d_in[6];
    float* out = (float*)d_out;

    cudaFuncSetAttribute(k3g, cudaFuncAttributeMaxDynamicSharedMemorySize, SMEMB);

    k1_gemm<<<dim3(H_N / 128, B_N / 128), 256>>>(x, W1, b1);
    k2_codes<<<(B_N * H_N) / 256, 256>>>();
    k2b_sort<<<B_N / 8, 256>>>();
    k3g<<<148, 512, SMEMB>>>(W2, b2);
    k5_out<<<B_N / 8, 256>>>(Wo, bo, out);
}

// round 8
// speedup vs baseline: 3.2076x; 1.2273x over previous
#include <cuda_runtime.h>
#include <cstdint>

#define B_N   65536
#define IN_N  512
#define H_N   1024
#define STEPS 10
#define BETA  0.9f
#define THR   1.0f

#define NSTRIPE 16                     // 1024 cols / 64
#define CHUNKB  32                     // b's per task (32 warps x 1)
#define NCHUNK  (B_N / CHUNKB)         // 2048
#define NTASK   (NSTRIPE * NCHUNK)     // 32768
#define LISTW2  648                    // padded sub-list length

// smem layout for k3g
#define SM_W2    0                     // 512 rows x 256B = 131072
#define SM_DUMMY 131072                // 256B zero row (offset 131072 = dummy)
#define SMEMB    (131072 + 512)

// ---------------- static scratch ----------------
__device__ float          g_cur1[(size_t)B_N * H_N];       // 268 MB
__device__ unsigned short g_code[B_N][H_N];                // 134 MB: layer-1 10-bit spike codes
__device__ unsigned       g_klist[B_N][2][2][LISTW2];      // 680 MB: [b][thalf][khalf] offsets klocal*256
__device__ unsigned short g_goff[B_N][2][2][32];           // padded group end-offsets
__device__ unsigned short g_s2code[B_N][H_N];              // 134 MB: layer-2 10-bit spike codes
__device__ unsigned       g_ticket;

// ---------------- K1: cur1 = x @ W1 + b1 (fp32 SIMT, validated) ----------------
__global__ __launch_bounds__(256) void k1_gemm(const float* __restrict__ X,
                                               const float* __restrict__ W1,
                                               const float* __restrict__ b1) {
    __shared__ float As[16][128];
    __shared__ float Bs[16][128];
    const int tid = threadIdx.x;
    const int tx = tid & 15, ty = tid >> 4;
    const int m0 = blockIdx.y * 128;
    const int n0 = blockIdx.x * 128;

    float acc[8][8];
#pragma unroll
    for (int i = 0; i < 8; i++)
#pragma unroll
        for (int j = 0; j < 8; j++) acc[i][j] = 0.f;

    for (int kc = 0; kc < IN_N; kc += 16) {
        float4 av[2], bv[2];
#pragma unroll
        for (int l = 0; l < 2; l++) {
            int f = tid + l * 256;
            int row = f >> 2, kq = (f & 3) * 4;
            av[l] = *(const float4*)&X[(size_t)(m0 + row) * IN_N + kc + kq];
            int kr = f >> 5, c4 = (f & 31) * 4;
            bv[l] = *(const float4*)&W1[(size_t)(kc + kr) * H_N + n0 + c4];
        }
        __syncthreads();
#pragma unroll
        for (int l = 0; l < 2; l++) {
            int f = tid + l * 256;
            int row = f >> 2, kq = (f & 3) * 4;
            As[kq + 0][row] = av[l].x; As[kq + 1][row] = av[l].y;
            As[kq + 2][row] = av[l].z; As[kq + 3][row] = av[l].w;
            int kr = f >> 5, c4 = (f & 31) * 4;
            *(float4*)&Bs[kr][c4] = bv[l];
        }
        __syncthreads();
#pragma unroll
        for (int kk = 0; kk < 16; kk++) {
            float a[8], bb[8];
            *(float4*)&a[0]  = *(float4*)&As[kk][ty * 8];
            *(float4*)&a[4]  = *(float4*)&As[kk][ty * 8 + 4];
            *(float4*)&bb[0] = *(float4*)&Bs[kk][tx * 8];
            *(float4*)&bb[4] = *(float4*)&Bs[kk][tx * 8 + 4];
#pragma unroll
            for (int i = 0; i < 8; i++)
#pragma unroll
                for (int j = 0; j < 8; j++) acc[i][j] += a[i] * bb[j];
        }
    }

    float bias[8];
#pragma unroll
    for (int j = 0; j < 8; j++) bias[j] = b1[n0 + tx * 8 + j];
#pragma unroll
    for (int i = 0; i < 8; i++) {
        int row = m0 + ty * 8 + i;
        float4 o0, o1;
        o0.x = acc[i][0] + bias[0]; o0.y = acc[i][1] + bias[1];
        o0.z = acc[i][2] + bias[2]; o0.w = acc[i][3] + bias[3];
        o1.x = acc[i][4] + bias[4]; o1.y = acc[i][5] + bias[5];
        o1.z = acc[i][6] + bias[6]; o1.w = acc[i][7] + bias[7];
        *(float4*)&g_cur1[(size_t)row * H_N + n0 + tx * 8]     = o0;
        *(float4*)&g_cur1[(size_t)row * H_N + n0 + tx * 8 + 4] = o1;
    }
}

// ---------------- K2: layer-1 LIF -> 10-bit spike code per (b,k); resets ticket ----------
__global__ __launch_bounds__(256) void k2_codes() {
    if (blockIdx.x == 0 && threadIdx.x == 0) g_ticket = 0;
    const int idx = blockIdx.x * 256 + threadIdx.x;
    const int b = idx >> 10, k = idx & (H_N - 1);
    const float c = g_cur1[(size_t)b * H_N + k];
    float m = 0.f;
    unsigned code = 0;
#pragma unroll
    for (int t = 0; t < STEPS; t++) {
        float r = (m > THR) ? THR : 0.f;
        m = BETA * m + c - r;
        code |= (m > THR) ? (1u << t) : 0u;
    }
    g_code[b][k] = (unsigned short)code;
}

// ---------------- K2b: per-(b, thalf, khalf) counting sort into 32 groups --------------
__global__ __launch_bounds__(256) void k2b_sort() {
    __shared__ unsigned scnt[8][32];
    const int wid  = threadIdx.x >> 5;
    const int lane = threadIdx.x & 31;
    const int b    = blockIdx.x * 8 + wid;
    const unsigned short* codes = g_code[b];
    const unsigned ltmask = (1u << lane) - 1u;
    const unsigned DUMMY = 131072u;            // zero row

    for (int h = 0; h < 2; h++) {
        for (int kh = 0; kh < 2; kh++) {
            unsigned* cnt = scnt[wid];
            cnt[lane] = 0;
            __syncwarp();
            for (int it = 0; it < 16; it++) {
                unsigned c = codes[kh * 512 + it * 32 + lane];
                unsigned g = (h ? (c >> 5) : c) & 31u;
                unsigned mm = __match_any_sync(0xFFFFFFFFu, g);
                if (g != 0 && (__ffs(mm) - 1) == lane) cnt[g] += __popc(mm);
                __syncwarp();
            }
            unsigned cg  = (lane > 0) ? cnt[lane] : 0u;
            unsigned pad = (cg + 3u) & ~3u;
            unsigned s = pad;
#pragma unroll
            for (int off = 1; off < 32; off <<= 1) {
                unsigned n = __shfl_up_sync(0xFFFFFFFFu, s, off);
                if (lane >= off) s += n;
            }
            if (lane >= 1) g_goff[b][h][kh][lane - 1] = (unsigned short)s;
            if (lane == 0) g_goff[b][h][kh][31] = 0;
            cnt[lane] = s - pad;
            __syncwarp();
            for (int it = 0; it < 16; it++) {
                unsigned c = codes[kh * 512 + it * 32 + lane];
                unsigned g = (h ? (c >> 5) : c) & 31u;
                unsigned mm = __match_any_sync(0xFFFFFFFFu, g);
                unsigned rank = __popc(mm & ltmask);
                unsigned pos0 = cnt[g];
                __syncwarp();
                if (g != 0) g_klist[b][h][kh][pos0 + rank] = (unsigned)(it * 32 + lane) * 256u;
                if (g != 0 && (__ffs(mm) - 1) == lane) cnt[g] = pos0 + __popc(mm);
                __syncwarp();
            }
            if (lane >= 1) {
                for (unsigned p = cnt[lane]; p < s; p++)
                    g_klist[b][h][kh][p] = DUMMY;
            }
            __syncwarp();
        }
    }
}

// ---------------- K3g: 64-col group-sum GEMM + fused layer-2 LIF -> s2 codes ----------
// Persistent CTAs (1024 thr = 32 warps). Task = (stripe of 64 cols, chunk of 32 b);
// warp owns ONE b, lane covers 2 cols (LDS.64). W2 staged per k-half (512 rows x 256B);
// all 10 step-sums live in registers across both k-phases (no smem scratch).
__global__ __launch_bounds__(1024, 1) void k3g(const float* __restrict__ W2,
                                               const float* __restrict__ b2) {
    extern __shared__ char smem[];
    __shared__ unsigned sTask;
    const int tid  = threadIdx.x;
    const int lane = tid & 31, wid = tid >> 5;
    const unsigned laneB = lane * 8;

    if (tid < 32) *(unsigned long long*)(smem + SM_DUMMY + tid * 8) = 0ull;
    __syncthreads();

    for (;;) {
        if (tid == 0) sTask = atomicAdd(&g_ticket, 1u);
        __syncthreads();
        const unsigned task = sTask;
        __syncthreads();
        if (task >= NTASK) break;
        const int stripe = task & (NSTRIPE - 1);   // consecutive tasks share a chunk
        const int chunk  = task >> 4;
        const int n0     = stripe * 64;
        const int b      = chunk * CHUNKB + wid;

        float2 S[2][5];
#pragma unroll
        for (int h = 0; h < 2; h++)
#pragma unroll
            for (int j = 0; j < 5; j++) S[h][j] = make_float2(0.f, 0.f);

        for (int kh = 0; kh < 2; kh++) {
            __syncthreads();                       // walks of previous phase done
            // stage rows [kh*512, +512) x 64 cols
            for (int i = tid; i < 512 * 16; i += 1024) {
                int k = i >> 4, q = i & 15;
                *(float4*)(smem + k * 256 + q * 16) =
                    *(const float4*)&W2[(size_t)(kh * 512 + k) * H_N + n0 + q * 4];
            }
            __syncthreads();

#pragma unroll
            for (int h = 0; h < 2; h++) {
                const unsigned* L = g_klist[b][h][kh];
                int ends  = (int)g_goff[b][h][kh][lane];
                int total = __shfl_sync(0xFFFFFFFFu, ends, 30);
                int ptr = 0, g = 0;
                int end_cur = __shfl_sync(0xFFFFFFFFu, ends, 0);
                uint4 kk = *(const uint4*)L;
                while (ptr < total) {
                    while (end_cur <= ptr) {
                        ++g;
                        end_cur = __shfl_sync(0xFFFFFFFFu, ends, g);
                    }
                    float2 G0 = make_float2(0.f, 0.f), G1 = make_float2(0.f, 0.f);
                    for (; ptr < end_cur; ptr += 4) {
                        uint4 nx = *(const uint4*)&L[ptr + 4];
                        float2 v0 = *(const float2*)(smem + kk.x + laneB);
                        float2 v1 = *(const float2*)(smem + kk.y + laneB);
                        float2 v2 = *(const float2*)(smem + kk.z + laneB);
                        float2 v3 = *(const float2*)(smem + kk.w + laneB);
                        G0.x += v0.x; G0.y += v0.y;
                        G1.x += v1.x; G1.y += v1.y;
                        G0.x += v2.x; G0.y += v2.y;
                        G1.x += v3.x; G1.y += v3.y;
                        kk = nx;
                    }
                    float2 G = make_float2(G0.x + G1.x, G0.y + G1.y);
                    int grp = g + 1;
                    if (grp & 1)  { S[h][0].x += G.x; S[h][0].y += G.y; }
                    if (grp & 2)  { S[h][1].x += G.x; S[h][1].y += G.y; }
                    if (grp & 4)  { S[h][2].x += G.x; S[h][2].y += G.y; }
                    if (grp & 8)  { S[h][3].x += G.x; S[h][3].y += G.y; }
                    if (grp & 16) { S[h][4].x += G.x; S[h][4].y += G.y; }
                }
            }
        }

        // LIF over all 10 steps; emit s2 spike codes (2 cols packed in one u32)
        {
            const float2 b2v = *(const float2*)&b2[n0 + lane * 2];
            float2 m2 = make_float2(0.f, 0.f);
            unsigned code = 0;
#pragma unroll
            for (int h = 0; h < 2; h++)
#pragma unroll
                for (int j = 0; j < 5; j++) {
                    float cx = S[h][j].x + b2v.x;
                    float cy = S[h][j].y + b2v.y;
                    float rx = (m2.x > THR) ? THR : 0.f;
                    float ry = (m2.y > THR) ? THR : 0.f;
                    m2.x = BETA * m2.x + cx - rx;
                    m2.y = BETA * m2.y + cy - ry;
                    int bit = h * 5 + j;
                    if (m2.x > THR) code |= 1u << bit;
                    if (m2.y > THR) code |= 1u << (16 + bit);
                }
            *(unsigned*)&g_s2code[b][n0 + lane * 2] = code;
        }
    }
}

// ---------------- K5: s2 codes -> Wo subset-sums, output LIF, mean ----------------
__global__ __launch_bounds__(256) void k5_out(const float* __restrict__ Wo,
                                              const float* __restrict__ bo,
                                              float* __restrict__ out) {
    __shared__ float sWo[H_N];
    for (int i = threadIdx.x; i < H_N; i += 256) sWo[i] = Wo[i];
    __syncthreads();
    const int wid = threadIdx.x >> 5, lane = threadIdx.x & 31;
    const int b = blockIdx.x * 8 + wid;

    float S[STEPS];
#pragma unroll
    for (int t = 0; t < STEPS; t++) S[t] = 0.f;

    for (int j = 0; j < 32; j++) {
        unsigned code = g_s2code[b][j * 32 + lane];
        float w = sWo[j * 32 + lane];
#pragma unroll
        for (int t = 0; t < STEPS; t++)
            S[t] += ((code >> t) & 1u) ? w : 0.f;
    }
#pragma unroll
    for (int t = 0; t < STEPS; t++)
#pragma unroll
        for (int off = 16; off; off >>= 1)
            S[t] += __shfl_down_sync(0xFFFFFFFFu, S[t], off);

    if (lane == 0) {
        const float bo0 = bo[0];
        float mo = 0.f, acc = 0.f;
#pragma unroll
        for (int t = 0; t < STEPS; t++) {
            float tot = S[t] + bo0;
            float r = (mo > THR) ? THR : 0.f;
            mo = BETA * mo + tot - r;
            acc += mo;
        }
        out[b] = acc * (1.f / STEPS);
    }
}

// ---------------- launcher ----------------
extern "C" void kernel_launch(void* const* d_in, const int* in_sizes, int n_in,
                              void* d_out, int out_size) {
    const float* x  = (const float*)d_in[0];
    const float* W1 = (const float*)d_in[1];
    const float* b1 = (const float*)d_in[2];
    const float* W2 = (const float*)d_in[3];
    const float* b2 = (const float*)d_in[4];
    const float* Wo = (const float*)d_in[5];
    const float* bo = (const float*)d_in[6];
    float* out = (float*)d_out;

    cudaFuncSetAttribute(k3g, cudaFuncAttributeMaxDynamicSharedMemorySize, SMEMB);

    k1_gemm<<<dim3(H_N / 128, B_N / 128), 256>>>(x, W1, b1);
    k2_codes<<<(B_N * H_N) / 256, 256>>>();
    k2b_sort<<<B_N / 8, 256>>>();
    k3g<<<148, 1024, SMEMB>>>(W2, b2);
    k5_out<<<B_N / 8, 256>>>(Wo, bo, out);
}

// round 9
// speedup vs baseline: 3.7867x; 1.1806x over previous
#include <cuda_runtime.h>
#include <cstdint>

#define B_N   65536
#define IN_N  512
#define H_N   1024
#define STEPS 10
#define BETA  0.9f
#define THR   1.0f

#define NSTRIPE 16                     // 1024 cols / 64
#define CHUNKB  32                     // b's per task (32 warps x 1)
#define NCHUNK  (B_N / CHUNKB)         // 2048
#define NTASK   (NSTRIPE * NCHUNK)     // 32768
#define LISTW   2080                   // worst-case 512 entries + padding + margin

// smem layout for k3g
#define SM_W2    0                     // 512 rows x 256B = 131072
#define SM_DUMMY 131072                // 512B zero row (offset 131072 = dummy)
#define SM_MASK  131584                // 1024 x u16 group-mask LUT
#define SMEMB    (131584 + 2048)

// ---------------- static scratch ----------------
__device__ float          g_cur1[(size_t)B_N * H_N];       // 268 MB
__device__ unsigned short g_code[B_N][H_N];                // 134 MB: layer-1 10-bit spike codes
__device__ unsigned       g_klist[B_N][2][LISTW];          // 1.09 GB: [b][khalf] offsets klocal*256
__device__ unsigned short g_gend[B_N][2][1024];            // 256 MB: cumulative group ends (per gid)
__device__ unsigned short g_s2code[B_N][H_N];              // 134 MB: layer-2 10-bit spike codes
__device__ unsigned       g_codebm[32];                    // presence bitmap of codes (idempotent)
__device__ unsigned short g_gidof[1024];                   // code -> gid
__device__ unsigned short g_maskof[1024];                  // gid  -> 10-bit mask (the code)
__device__ unsigned       g_ngids;
__device__ unsigned       g_ticket;

// ---------------- K1: cur1 = x @ W1 + b1 (fp32 SIMT, validated) ----------------
__global__ __launch_bounds__(256) void k1_gemm(const float* __restrict__ X,
                                               const float* __restrict__ W1,
                                               const float* __restrict__ b1) {
    __shared__ float As[16][128];
    __shared__ float Bs[16][128];
    const int tid = threadIdx.x;
    const int tx = tid & 15, ty = tid >> 4;
    const int m0 = blockIdx.y * 128;
    const int n0 = blockIdx.x * 128;

    float acc[8][8];
#pragma unroll
    for (int i = 0; i < 8; i++)
#pragma unroll
        for (int j = 0; j < 8; j++) acc[i][j] = 0.f;

    for (int kc = 0; kc < IN_N; kc += 16) {
        float4 av[2], bv[2];
#pragma unroll
        for (int l = 0; l < 2; l++) {
            int f = tid + l * 256;
            int row = f >> 2, kq = (f & 3) * 4;
            av[l] = *(const float4*)&X[(size_t)(m0 + row) * IN_N + kc + kq];
            int kr = f >> 5, c4 = (f & 31) * 4;
            bv[l] = *(const float4*)&W1[(size_t)(kc + kr) * H_N + n0 + c4];
        }
        __syncthreads();
#pragma unroll
        for (int l = 0; l < 2; l++) {
            int f = tid + l * 256;
            int row = f >> 2, kq = (f & 3) * 4;
            As[kq + 0][row] = av[l].x; As[kq + 1][row] = av[l].y;
            As[kq + 2][row] = av[l].z; As[kq + 3][row] = av[l].w;
            int kr = f >> 5, c4 = (f & 31) * 4;
            *(float4*)&Bs[kr][c4] = bv[l];
        }
        __syncthreads();
#pragma unroll
        for (int kk = 0; kk < 16; kk++) {
            float a[8], bb[8];
            *(float4*)&a[0]  = *(float4*)&As[kk][ty * 8];
            *(float4*)&a[4]  = *(float4*)&As[kk][ty * 8 + 4];
            *(float4*)&bb[0] = *(float4*)&Bs[kk][tx * 8];
            *(float4*)&bb[4] = *(float4*)&Bs[kk][tx * 8 + 4];
#pragma unroll
            for (int i = 0; i < 8; i++)
#pragma unroll
                for (int j = 0; j < 8; j++) acc[i][j] += a[i] * bb[j];
        }
    }

    float bias[8];
#pragma unroll
    for (int j = 0; j < 8; j++) bias[j] = b1[n0 + tx * 8 + j];
#pragma unroll
    for (int i = 0; i < 8; i++) {
        int row = m0 + ty * 8 + i;
        float4 o0, o1;
        o0.x = acc[i][0] + bias[0]; o0.y = acc[i][1] + bias[1];
        o0.z = acc[i][2] + bias[2]; o0.w = acc[i][3] + bias[3];
        o1.x = acc[i][4] + bias[4]; o1.y = acc[i][5] + bias[5];
        o1.z = acc[i][6] + bias[6]; o1.w = acc[i][7] + bias[7];
        *(float4*)&g_cur1[(size_t)row * H_N + n0 + tx * 8]     = o0;
        *(float4*)&g_cur1[(size_t)row * H_N + n0 + tx * 8 + 4] = o1;
    }
}

// ---------------- K2: layer-1 LIF -> 10-bit codes + code-presence bitmap ----------------
__global__ __launch_bounds__(256) void k2_codes() {
    __shared__ unsigned bm[32];
    if (blockIdx.x == 0 && threadIdx.x == 0) g_ticket = 0;
    if (threadIdx.x < 32) bm[threadIdx.x] = 0;
    __syncthreads();
    const int idx = blockIdx.x * 256 + threadIdx.x;
    const int b = idx >> 10, k = idx & (H_N - 1);
    const float c = g_cur1[(size_t)b * H_N + k];
    float m = 0.f;
    unsigned code = 0;
#pragma unroll
    for (int t = 0; t < STEPS; t++) {
        float r = (m > THR) ? THR : 0.f;
        m = BETA * m + c - r;
        code |= (m > THR) ? (1u << t) : 0u;
    }
    g_code[b][k] = (unsigned short)code;
    atomicOr(&bm[code >> 5], 1u << (code & 31));
    __syncthreads();
    if (threadIdx.x < 32 && bm[threadIdx.x])
        atomicOr(&g_codebm[threadIdx.x], bm[threadIdx.x]);
}

// ---------------- K2a: build code dictionary (gid per occurring nonzero code) ----------
__global__ void k2a_dict() {
    if (threadIdx.x == 0) {
        int gid = 0;
        for (int c = 1; c < 1024; c++) {
            if ((g_codebm[c >> 5] >> (c & 31)) & 1u) {
                g_gidof[c] = (unsigned short)gid;
                g_maskof[gid] = (unsigned short)c;
                gid++;
            }
        }
        g_ngids = (unsigned)gid;
    }
}

// ---------------- K2b: per-(b,khalf) counting sort by gid ----------------
// warp per b; groups 4-aligned, padded with DUMMY (zero row). code 0 excluded.
__global__ __launch_bounds__(256) void k2b_sort() {
    __shared__ int hist[8][1024];
    const int wid  = threadIdx.x >> 5;
    const int lane = threadIdx.x & 31;
    const int b    = blockIdx.x * 8 + wid;
    const int ng   = (int)g_ngids;
    const unsigned short* codes = g_code[b];
    const unsigned ltmask = (1u << lane) - 1u;
    const unsigned DUMMY = 131072u;

    for (int kh = 0; kh < 2; kh++) {
        for (int i = lane; i < ng; i += 32) hist[wid][i] = 0;
        __syncwarp();
        // pass 1: counts (smem atomics; order-independent)
        for (int it = 0; it < 16; it++) {
            unsigned c = codes[kh * 512 + it * 32 + lane];
            if (c) atomicAdd(&hist[wid][g_gidof[c]], 1);
        }
        __syncwarp();
        // scan of 4-aligned padded counts -> ends (gmem) + start cursors (smem)
        int carry = 0;
        for (int base = 0; base < ng; base += 32) {
            int idx = base + lane;
            int cv = (idx < ng) ? hist[wid][idx] : 0;
            int pv = cv ? ((cv + 3) & ~3) : 0;
            int s = pv;
#pragma unroll
            for (int off = 1; off < 32; off <<= 1) {
                int n = __shfl_up_sync(0xFFFFFFFFu, s, off);
                if (lane >= off) s += n;
            }
            s += carry;
            if (idx < ng) {
                g_gend[b][kh][idx] = (unsigned short)s;
                hist[wid][idx] = s - pv;          // start cursor
            }
            carry = __shfl_sync(0xFFFFFFFFu, s, 31);
        }
        __syncwarp();
        // pass 2: deterministic scatter (byte offsets klocal*256)
        for (int it = 0; it < 16; it++) {
            unsigned c = codes[kh * 512 + it * 32 + lane];
            int gid = c ? (int)g_gidof[c] : -1;
            unsigned mm = __match_any_sync(0xFFFFFFFFu, gid);
            unsigned rank = __popc(mm & ltmask);
            int pos0 = (gid >= 0) ? hist[wid][gid] : 0;
            __syncwarp();
            if (gid >= 0) g_klist[b][kh][pos0 + rank] = (unsigned)(it * 32 + lane) * 256u;
            if (gid >= 0 && (__ffs(mm) - 1) == lane) hist[wid][gid] = pos0 + __popc(mm);
            __syncwarp();
        }
        // pad fill to 4-alignment (end = round-up of final cursor)
        for (int i = lane; i < ng; i += 32) {
            int cur = hist[wid][i], end = (cur + 3) & ~3;
            for (int p = cur; p < end; p++) g_klist[b][kh][p] = DUMMY;
        }
        __syncwarp();
    }
}

// ---------------- K3g: single-walk group-sum GEMM + fused layer-2 LIF -> s2 codes ------
// Persistent CTAs (1024 thr = 32 warps). Task = (stripe of 64 cols, chunk of 32 b);
// warp owns ONE b, lane covers 2 cols (LDS.64). W2 staged per k-half. Each active k
// walked ONCE; its group's 10-bit mask scatters G into all 10 step-sums (registers).
__global__ __launch_bounds__(1024, 1) void k3g(const float* __restrict__ W2,
                                               const float* __restrict__ b2) {
    extern __shared__ char smem[];
    __shared__ unsigned sTask;
    const int tid  = threadIdx.x;
    const int lane = tid & 31, wid = tid >> 5;
    const unsigned laneB = lane * 8;
    const int ng = (int)g_ngids;

    if (tid < 64) *(unsigned long long*)(smem + SM_DUMMY + tid * 8) = 0ull;
    { int i = tid; if (i < 1024) ((unsigned short*)(smem + SM_MASK))[i] = g_maskof[i]; }
    __syncthreads();

    for (;;) {
        if (tid == 0) sTask = atomicAdd(&g_ticket, 1u);
        __syncthreads();
        const unsigned task = sTask;
        __syncthreads();
        if (task >= NTASK) break;
        const int stripe = task & (NSTRIPE - 1);   // consecutive tasks share a chunk
        const int chunk  = task >> 4;
        const int n0     = stripe * 64;
        const int b      = chunk * CHUNKB + wid;

        float2 S[STEPS];
#pragma unroll
        for (int t = 0; t < STEPS; t++) S[t] = make_float2(0.f, 0.f);

        for (int kh = 0; kh < 2; kh++) {
            __syncthreads();                       // walks of previous phase done
            for (int i = tid; i < 512 * 16; i += 1024) {
                int k = i >> 4, q = i & 15;
                *(float4*)(smem + k * 256 + q * 16) =
                    *(const float4*)&W2[(size_t)(kh * 512 + k) * H_N + n0 + q * 4];
            }
            __syncthreads();

            const unsigned short* ends = g_gend[b][kh];
            const unsigned* L = g_klist[b][kh];
            int ptr = 0;
            uint4 kk = *(const uint4*)L;
            for (int gb = 0; gb < ng; gb += 32) {
                int e = 0;
                if (gb + lane < ng) e = (int)ends[gb + lane];
                const int lim = (ng - gb < 32) ? (ng - gb) : 32;
                for (int g2 = 0; g2 < lim; g2++) {
                    int end = __shfl_sync(0xFFFFFFFFu, e, g2);
                    if (end <= ptr) continue;
                    float2 G0 = make_float2(0.f, 0.f), G1 = make_float2(0.f, 0.f);
                    for (; ptr < end; ptr += 4) {
                        uint4 nx = *(const uint4*)&L[ptr + 4];
                        float2 v0 = *(const float2*)(smem + kk.x + laneB);
                        float2 v1 = *(const float2*)(smem + kk.y + laneB);
                        float2 v2 = *(const float2*)(smem + kk.z + laneB);
                        float2 v3 = *(const float2*)(smem + kk.w + laneB);
                        G0.x += v0.x; G0.y += v0.y;
                        G1.x += v1.x; G1.y += v1.y;
                        G0.x += v2.x; G0.y += v2.y;
                        G1.x += v3.x; G1.y += v3.y;
                        kk = nx;
                    }
                    const float gx = G0.x + G1.x, gy = G0.y + G1.y;
                    const unsigned mask = ((const unsigned short*)(smem + SM_MASK))[gb + g2];
                    if (mask & 1u)   { S[0].x += gx; S[0].y += gy; }
                    if (mask & 2u)   { S[1].x += gx; S[1].y += gy; }
                    if (mask & 4u)   { S[2].x += gx; S[2].y += gy; }
                    if (mask & 8u)   { S[3].x += gx; S[3].y += gy; }
                    if (mask & 16u)  { S[4].x += gx; S[4].y += gy; }
                    if (mask & 32u)  { S[5].x += gx; S[5].y += gy; }
                    if (mask & 64u)  { S[6].x += gx; S[6].y += gy; }
                    if (mask & 128u) { S[7].x += gx; S[7].y += gy; }
                    if (mask & 256u) { S[8].x += gx; S[8].y += gy; }
                    if (mask & 512u) { S[9].x += gx; S[9].y += gy; }
                }
            }
        }

        // LIF over all 10 steps; emit s2 spike codes (2 cols packed in one u32)
        {
            const float2 b2v = *(const float2*)&b2[n0 + lane * 2];
            float2 m2 = make_float2(0.f, 0.f);
            unsigned code = 0;
#pragma unroll
            for (int t = 0; t < STEPS; t++) {
                float cx = S[t].x + b2v.x;
                float cy = S[t].y + b2v.y;
                float rx = (m2.x > THR) ? THR : 0.f;
                float ry = (m2.y > THR) ? THR : 0.f;
                m2.x = BETA * m2.x + cx - rx;
                m2.y = BETA * m2.y + cy - ry;
                if (m2.x > THR) code |= 1u << t;
                if (m2.y > THR) code |= 1u << (16 + t);
            }
            *(unsigned*)&g_s2code[b][n0 + lane * 2] = code;
        }
    }
}

// ---------------- K5: s2 codes -> Wo subset-sums, output LIF, mean ----------------
__global__ __launch_bounds__(256) void k5_out(const float* __restrict__ Wo,
                                              const float* __restrict__ bo,
                                              float* __restrict__ out) {
    __shared__ float sWo[H_N];
    for (int i = threadIdx.x; i < H_N; i += 256) sWo[i] = Wo[i];
    __syncthreads();
    const int wid = threadIdx.x >> 5, lane = threadIdx.x & 31;
    const int b = blockIdx.x * 8 + wid;

    float S[STEPS];
#pragma unroll
    for (int t = 0; t < STEPS; t++) S[t] = 0.f;

    for (int j = 0; j < 32; j++) {
        unsigned code = g_s2code[b][j * 32 + lane];
        float w = sWo[j * 32 + lane];
#pragma unroll
        for (int t = 0; t < STEPS; t++)
            S[t] += ((code >> t) & 1u) ? w : 0.f;
    }
#pragma unroll
    for (int t = 0; t < STEPS; t++)
#pragma unroll
        for (int off = 16; off; off >>= 1)
            S[t] += __shfl_down_sync(0xFFFFFFFFu, S[t], off);

    if (lane == 0) {
        const float bo0 = bo[0];
        float mo = 0.f, acc = 0.f;
#pragma unroll
        for (int t = 0; t < STEPS; t++) {
            float tot = S[t] + bo0;
            float r = (mo > THR) ? THR : 0.f;
            mo = BETA * mo + tot - r;
            acc += mo;
        }
        out[b] = acc * (1.f / STEPS);
    }
}

// ---------------- launcher ----------------
extern "C" void kernel_launch(void* const* d_in, const int* in_sizes, int n_in,
                              void* d_out, int out_size) {
    const float* x  = (const float*)d_in[0];
    const float* W1 = (const float*)d_in[1];
    const float* b1 = (const float*)d_in[2];
    const float* W2 = (const float*)d_in[3];
    const float* b2 = (const float*)d_in[4];
    const float* Wo = (const float*)d_in[5];
    const float* bo = (const float*)d_in[6];
    float* out = (float*)d_out;

    cudaFuncSetAttribute(k3g, cudaFuncAttributeMaxDynamicSharedMemorySize, SMEMB);

    k1_gemm<<<dim3(H_N / 128, B_N / 128), 256>>>(x, W1, b1);
    k2_codes<<<(B_N * H_N) / 256, 256>>>();
    k2a_dict<<<1, 32>>>();
    k2b_sort<<<B_N / 8, 256>>>();
    k3g<<<148, 1024, SMEMB>>>(W2, b2);
    k5_out<<<B_N / 8, 256>>>(Wo, bo, out);
}